// round 6
// baseline (speedup 1.0000x reference)
#include <cuda_runtime.h>
#include <math.h>

#define Bz 2
#define Sq 2048
#define Dm 1024
#define Hn 16
#define DH 64
#define NREL 129
#define BHN (Bz*Hn)

typedef unsigned long long ull;

__device__ float g_Q[BHN * Sq * DH];
__device__ float g_K[BHN * Sq * DH];
__device__ float g_V[BHN * Sq * DH];

__device__ __forceinline__ ull pack2(float lo, float hi) {
    ull r; asm("mov.b64 %0, {%1, %2};" : "=l"(r) : "f"(lo), "f"(hi)); return r;
}
__device__ __forceinline__ float2 unpack2(ull v) {
    float2 r; asm("mov.b64 {%0, %1}, %2;" : "=f"(r.x), "=f"(r.y) : "l"(v)); return r;
}
__device__ __forceinline__ void fma2(ull& a, ull x, ull y) {
    asm("fma.rn.f32x2 %0, %1, %2, %0;" : "+l"(a) : "l"(x), "l"(y));
}
__device__ __forceinline__ ull mul2(ull x, ull y) {
    ull r; asm("mul.rn.f32x2 %0, %1, %2;" : "=l"(r) : "l"(x), "l"(y)); return r;
}
__device__ __forceinline__ void cp16(float* dst, const float* src) {
    unsigned a = (unsigned)__cvta_generic_to_shared(dst);
    asm volatile("cp.async.cg.shared.global [%0], [%1], 16;" :: "r"(a), "l"(src) : "memory");
}

// ---------------------------------------------------------------------------
// Kernel 1: QKV projection. 128x128 tile, k-step 16, 8x8 micro, FFMA2.
// grid (8, 32, 3), block 256, 2 CTAs/SM.  (unchanged from round 5)
// ---------------------------------------------------------------------------
__global__ __launch_bounds__(256, 2)
void qkv_proj_kernel(const float* __restrict__ Xq, const float* __restrict__ Xk,
                     const float* __restrict__ Xv,
                     const float* __restrict__ Wq, const float* __restrict__ Wk,
                     const float* __restrict__ Wv,
                     const float* __restrict__ bq, const float* __restrict__ bk,
                     const float* __restrict__ bv)
{
    const float* X; const float* W; const float* bias; float* outp;
    if (blockIdx.z == 0)      { X = Xq; W = Wq; bias = bq; outp = g_Q; }
    else if (blockIdx.z == 1) { X = Xk; W = Wk; bias = bk; outp = g_K; }
    else                      { X = Xv; W = Wv; bias = bv; outp = g_V; }

    __shared__ __align__(16) float Xs[16][132];
    __shared__ __align__(16) float Ws[16][132];

    const int tid = threadIdx.x;
    const int tx = tid & 15, ty = tid >> 4;
    const int m0 = blockIdx.y * 128, n0 = blockIdx.x * 128;
    const int xr = tid & 127, xk = (tid >> 7) * 8;
    const int wr = tid >> 4,  wc = (tid & 15) * 8;

    ull acc[8][4];
    #pragma unroll
    for (int i = 0; i < 8; i++)
        #pragma unroll
        for (int j = 0; j < 4; j++) acc[i][j] = 0ull;

    float4 xa = *(const float4*)&X[(size_t)(m0 + xr) * Dm + xk];
    float4 xb = *(const float4*)&X[(size_t)(m0 + xr) * Dm + xk + 4];
    float4 wa = *(const float4*)&W[(size_t)wr * Dm + n0 + wc];
    float4 wb = *(const float4*)&W[(size_t)wr * Dm + n0 + wc + 4];

    for (int t = 0; t < 64; t++) {
        Xs[xk + 0][xr] = xa.x; Xs[xk + 1][xr] = xa.y;
        Xs[xk + 2][xr] = xa.z; Xs[xk + 3][xr] = xa.w;
        Xs[xk + 4][xr] = xb.x; Xs[xk + 5][xr] = xb.y;
        Xs[xk + 6][xr] = xb.z; Xs[xk + 7][xr] = xb.w;
        *(float4*)&Ws[wr][wc] = wa;
        *(float4*)&Ws[wr][wc + 4] = wb;
        __syncthreads();
        if (t < 63) {
            const int k0 = (t + 1) * 16;
            xa = *(const float4*)&X[(size_t)(m0 + xr) * Dm + k0 + xk];
            xb = *(const float4*)&X[(size_t)(m0 + xr) * Dm + k0 + xk + 4];
            wa = *(const float4*)&W[(size_t)(k0 + wr) * Dm + n0 + wc];
            wb = *(const float4*)&W[(size_t)(k0 + wr) * Dm + n0 + wc + 4];
        }
        #pragma unroll
        for (int kk = 0; kk < 16; kk++) {
            float4 a0 = *(const float4*)&Xs[kk][ty * 8];
            float4 a1 = *(const float4*)&Xs[kk][ty * 8 + 4];
            ulonglong2 b0 = *(const ulonglong2*)&Ws[kk][tx * 4];
            ulonglong2 b1 = *(const ulonglong2*)&Ws[kk][64 + tx * 4];
            ull p;
            p = pack2(a0.x, a0.x); fma2(acc[0][0], p, b0.x); fma2(acc[0][1], p, b0.y); fma2(acc[0][2], p, b1.x); fma2(acc[0][3], p, b1.y);
            p = pack2(a0.y, a0.y); fma2(acc[1][0], p, b0.x); fma2(acc[1][1], p, b0.y); fma2(acc[1][2], p, b1.x); fma2(acc[1][3], p, b1.y);
            p = pack2(a0.z, a0.z); fma2(acc[2][0], p, b0.x); fma2(acc[2][1], p, b0.y); fma2(acc[2][2], p, b1.x); fma2(acc[2][3], p, b1.y);
            p = pack2(a0.w, a0.w); fma2(acc[3][0], p, b0.x); fma2(acc[3][1], p, b0.y); fma2(acc[3][2], p, b1.x); fma2(acc[3][3], p, b1.y);
            p = pack2(a1.x, a1.x); fma2(acc[4][0], p, b0.x); fma2(acc[4][1], p, b0.y); fma2(acc[4][2], p, b1.x); fma2(acc[4][3], p, b1.y);
            p = pack2(a1.y, a1.y); fma2(acc[5][0], p, b0.x); fma2(acc[5][1], p, b0.y); fma2(acc[5][2], p, b1.x); fma2(acc[5][3], p, b1.y);
            p = pack2(a1.z, a1.z); fma2(acc[6][0], p, b0.x); fma2(acc[6][1], p, b0.y); fma2(acc[6][2], p, b1.x); fma2(acc[6][3], p, b1.y);
            p = pack2(a1.w, a1.w); fma2(acc[7][0], p, b0.x); fma2(acc[7][1], p, b0.y); fma2(acc[7][2], p, b1.x); fma2(acc[7][3], p, b1.y);
        }
        __syncthreads();
    }

    float4 bl = *(const float4*)&bias[n0 + tx * 4];
    float4 bh = *(const float4*)&bias[n0 + 64 + tx * 4];
    const int h0 = n0 >> 6;
    #pragma unroll
    for (int i = 0; i < 8; i++) {
        const int m = m0 + ty * 8 + i, bb = m >> 11, s = m & 2047;
        float2 c0 = unpack2(acc[i][0]), c1 = unpack2(acc[i][1]);
        float4 v = make_float4(c0.x + bl.x, c0.y + bl.y, c1.x + bl.z, c1.y + bl.w);
        *(float4*)&outp[((size_t)((bb * Hn + h0) * Sq + s)) * DH + tx * 4] = v;
        c0 = unpack2(acc[i][2]); c1 = unpack2(acc[i][3]);
        v = make_float4(c0.x + bh.x, c0.y + bh.y, c1.x + bh.z, c1.y + bh.w);
        *(float4*)&outp[((size_t)((bb * Hn + h0 + 1) * Sq + s)) * DH + tx * 4] = v;
    }
}

// ---------------------------------------------------------------------------
// Kernel 2: flash attention, Bq=128, Bk=64, 512 threads, 4x4 micro FFMA2.
// grid (16, 32), 16 warps/SM for latency hiding.
// ---------------------------------------------------------------------------
#define QT 0        // [64][136] Q transposed [d][r]
#define KT 8704     // [64][68]  K transposed [d][j]
#define VS 13056    // [2][64][68] V natural [j][dc]
#define PS 21760    // [64][128] P transposed [j][r], unit-swizzled
#define PB 29952    // [128][132] bias lookup
#define SMF 46848

extern __shared__ __align__(16) float sm[];

__global__ __launch_bounds__(512, 1)
void attn_kernel(const float* __restrict__ mask,
                 const float* __restrict__ rel,
                 float* __restrict__ out)
{
    float* Qt = sm + QT;
    float* Kt = sm + KT;
    float* Vs = sm + VS;
    float* Ps = sm + PS;
    float* pb = sm + PB;
    float* relT = sm + KT;   // [64][144] overlay, dead after pb compute

    const int tid = threadIdx.x;
    const int tx = tid & 15, ty = tid >> 4;   // ty 0..31 -> 4 rows each
    const int bh = blockIdx.y, b = bh >> 4, h = bh & 15;
    const int q0 = blockIdx.x * 128;

    const float* Qg = g_Q + (size_t)bh * (Sq * DH);
    const float* Kg = g_K + (size_t)bh * (Sq * DH);
    const float* Vg = g_V + (size_t)bh * (Sq * DH);
    const float* maskb = mask + (size_t)b * Sq;

    // ---- stage Q transposed ----
    {
        const int qr = tid & 127, qc = (tid >> 7) * 16;
        #pragma unroll
        for (int u = 0; u < 4; u++) {
            int d = qc + u * 4;
            float4 v = *(const float4*)&Qg[(size_t)(q0 + qr) * DH + d];
            Qt[(d + 0) * 136 + qr] = v.x; Qt[(d + 1) * 136 + qr] = v.y;
            Qt[(d + 2) * 136 + qr] = v.z; Qt[(d + 3) * 136 + qr] = v.w;
        }
    }
    // ---- stage rel transposed [d][t], zero-pad t in [129,144) ----
    for (int i = tid; i < 64 * 15; i += 512)
        relT[(i / 15) * 144 + 129 + (i % 15)] = 0.f;
    for (int i = tid; i < NREL * 16; i += 512) {
        int t = i >> 4, d4 = (i & 15) * 4;
        float4 v = *(const float4*)&rel[t * DH + d4];
        relT[(d4 + 0) * 144 + t] = v.x; relT[(d4 + 1) * 144 + t] = v.y;
        relT[(d4 + 2) * 144 + t] = v.z; relT[(d4 + 3) * 144 + t] = v.w;
    }
    __syncthreads();

    // ---- pb[r][t] = q_r . rel_t  (4 rows per thread, packed f32x2) ----
    {
        ull pa[2][9];
        #pragma unroll
        for (int rp = 0; rp < 2; rp++)
            #pragma unroll
            for (int tt = 0; tt < 9; tt++) pa[rp][tt] = 0ull;
        for (int d = 0; d < DH; d++) {
            ulonglong2 qa = *(const ulonglong2*)&Qt[d * 136 + ty * 4];
            #pragma unroll
            for (int tt = 0; tt < 9; tt++) {
                float rv = relT[d * 144 + tx + 16 * tt];
                ull rv2 = pack2(rv, rv);
                fma2(pa[0][tt], qa.x, rv2);
                fma2(pa[1][tt], qa.y, rv2);
            }
        }
        #pragma unroll
        for (int tt = 0; tt < 9; tt++) {
            int t = tx + 16 * tt;
            if (t < 132) {
                #pragma unroll
                for (int rp = 0; rp < 2; rp++) {
                    float2 f = unpack2(pa[rp][tt]);
                    pb[(ty * 4 + 2 * rp)     * 132 + t] = f.x;
                    pb[(ty * 4 + 2 * rp + 1) * 132 + t] = f.y;
                }
            }
        }
    }
    __syncthreads();

    // constant-clip biases per row
    float pLo[4], pHi[4];
    #pragma unroll
    for (int i = 0; i < 4; i++) {
        pLo[i] = pb[(ty * 4 + i) * 132];
        pHi[i] = pb[(ty * 4 + i) * 132 + 128];
    }

    // ---- prologue loads: V0 via cp.async, K0 via LDG ----
    const int krow = tid & 63, kd0 = (tid >> 6) * 8;
    #pragma unroll
    for (int c = 0; c < 2; c++)
        cp16(&Vs[krow * 68 + kd0 + 4 * c], &Vg[(size_t)krow * DH + kd0 + 4 * c]);
    asm volatile("cp.async.commit_group;" ::: "memory");
    float4 kr4[2];
    #pragma unroll
    for (int c = 0; c < 2; c++)
        kr4[c] = *(const float4*)&Kg[(size_t)krow * DH + kd0 + 4 * c];

    ull o[4][2];
    float m_i[4], l_i[4];
    #pragma unroll
    for (int i = 0; i < 4; i++) {
        o[i][0] = 0ull; o[i][1] = 0ull; m_i[i] = -INFINITY; l_i[i] = 0.f;
    }

    for (int kt = 0; kt < 32; kt++) {
        const int buf = kt & 1;
        const int k0 = kt * 64;
        __syncthreads();   // prev tile consumers done

        #pragma unroll
        for (int c = 0; c < 2; c++) {
            int d = kd0 + 4 * c;
            Kt[(d + 0) * 68 + krow] = kr4[c].x; Kt[(d + 1) * 68 + krow] = kr4[c].y;
            Kt[(d + 2) * 68 + krow] = kr4[c].z; Kt[(d + 3) * 68 + krow] = kr4[c].w;
        }
        if (kt < 31) {
            const float* Vn = Vg + (size_t)(k0 + 64) * DH;
            const float* Kn = Kg + (size_t)(k0 + 64) * DH;
            float* Vd = Vs + (buf ^ 1) * 4352;
            #pragma unroll
            for (int c = 0; c < 2; c++)
                cp16(&Vd[krow * 68 + kd0 + 4 * c], &Vn[(size_t)krow * DH + kd0 + 4 * c]);
            asm volatile("cp.async.commit_group;" ::: "memory");
            #pragma unroll
            for (int c = 0; c < 2; c++)
                kr4[c] = *(const float4*)&Kn[(size_t)krow * DH + kd0 + 4 * c];
            asm volatile("cp.async.wait_group 1;" ::: "memory");
        } else {
            asm volatile("cp.async.wait_group 0;" ::: "memory");
        }
        __syncthreads();   // Kt + Vs[buf] visible

        // ---- scores: 4 rows x 4 cols ----
        ull acc[4][2];
        #pragma unroll
        for (int i = 0; i < 4; i++) { acc[i][0] = 0ull; acc[i][1] = 0ull; }
        #pragma unroll 8
        for (int d = 0; d < DH; d++) {
            float4 a = *(const float4*)&Qt[d * 136 + ty * 4];
            ulonglong2 bv = *(const ulonglong2*)&Kt[d * 68 + tx * 4];
            ull p;
            p = pack2(a.x, a.x); fma2(acc[0][0], p, bv.x); fma2(acc[0][1], p, bv.y);
            p = pack2(a.y, a.y); fma2(acc[1][0], p, bv.x); fma2(acc[1][1], p, bv.y);
            p = pack2(a.z, a.z); fma2(acc[2][0], p, bv.x); fma2(acc[2][1], p, bv.y);
            p = pack2(a.w, a.w); fma2(acc[3][0], p, bv.x); fma2(acc[3][1], p, bv.y);
        }

        // ---- softmax ----
        float4 mk4 = *(const float4*)&maskb[k0 + tx * 4];
        const float mkf[4] = {mk4.x, mk4.y, mk4.z, mk4.w};
        const int ddmin = k0 - (q0 + 127), ddmax = k0 + 63 - q0;
        const bool gen = (ddmax > -64) && (ddmin < 64);
        float pv[4][4];
        #pragma unroll
        for (int i = 0; i < 4; i++) {
            float2 f0 = unpack2(acc[i][0]), f1 = unpack2(acc[i][1]);
            float s[4] = {f0.x, f0.y, f1.x, f1.y};
            if (gen) {
                const int rg = q0 + ty * 4 + i;
                #pragma unroll
                for (int jj = 0; jj < 4; jj++) {
                    int dd = k0 + tx * 4 + jj - rg;
                    dd = dd < -64 ? -64 : (dd > 64 ? 64 : dd);
                    s[jj] = (s[jj] + pb[(ty * 4 + i) * 132 + dd + 64]) * 0.125f + mkf[jj];
                }
            } else {
                const float bi = (ddmin >= 64) ? pHi[i] : pLo[i];
                #pragma unroll
                for (int jj = 0; jj < 4; jj++)
                    s[jj] = (s[jj] + bi) * 0.125f + mkf[jj];
            }
            float mx = fmaxf(fmaxf(s[0], s[1]), fmaxf(s[2], s[3]));
            #pragma unroll
            for (int off = 8; off; off >>= 1)
                mx = fmaxf(mx, __shfl_xor_sync(0xffffffffu, mx, off, 16));
            const float mnew = fmaxf(m_i[i], mx);
            const float alpha = __expf(m_i[i] - mnew);
            float rs = 0.f;
            #pragma unroll
            for (int jj = 0; jj < 4; jj++) {
                float p = __expf(s[jj] - mnew);
                pv[i][jj] = p; rs += p;
            }
            #pragma unroll
            for (int off = 8; off; off >>= 1)
                rs += __shfl_xor_sync(0xffffffffu, rs, off, 16);
            l_i[i] = l_i[i] * alpha + rs;
            m_i[i] = mnew;
            ull a2 = pack2(alpha, alpha);
            o[i][0] = mul2(o[i][0], a2);
            o[i][1] = mul2(o[i][1], a2);
        }

        // ---- stage P transposed, unit = ty ^ tx ----
        {
            const int u = (ty ^ tx) * 4;
            #pragma unroll
            for (int jj = 0; jj < 4; jj++)
                *(float4*)(Ps + (tx * 4 + jj) * 128 + u) =
                    make_float4(pv[0][jj], pv[1][jj], pv[2][jj], pv[3][jj]);
        }
        __syncthreads();

        // ---- O += P V ----
        const float* Vb = Vs + buf * 4352;
        #pragma unroll 8
        for (int j = 0; j < 64; j++) {
            float4 a = *(const float4*)(Ps + j * 128 + 4 * (ty ^ (j >> 2)));
            ulonglong2 bv = *(const ulonglong2*)&Vb[j * 68 + tx * 4];
            ull p;
            p = pack2(a.x, a.x); fma2(o[0][0], p, bv.x); fma2(o[0][1], p, bv.y);
            p = pack2(a.y, a.y); fma2(o[1][0], p, bv.x); fma2(o[1][1], p, bv.y);
            p = pack2(a.z, a.z); fma2(o[2][0], p, bv.x); fma2(o[2][1], p, bv.y);
            p = pack2(a.w, a.w); fma2(o[3][0], p, bv.x); fma2(o[3][1], p, bv.y);
        }
    }

    #pragma unroll
    for (int i = 0; i < 4; i++) {
        const int qg = q0 + ty * 4 + i;
        const float inv = 1.f / l_i[i];
        float2 c0 = unpack2(o[i][0]), c1 = unpack2(o[i][1]);
        float4 v = make_float4(c0.x * inv, c0.y * inv, c1.x * inv, c1.y * inv);
        *(float4*)&out[((size_t)(b * Sq + qg)) * Dm + h * DH + tx * 4] = v;
    }
}

extern "C" void kernel_launch(void* const* d_in, const int* in_sizes, int n_in,
                              void* d_out, int out_size)
{
    const float* query = (const float*)d_in[0];
    const float* key   = (const float*)d_in[1];
    const float* value = (const float*)d_in[2];
    const float* mask  = (const float*)d_in[3];
    const float* Wq    = (const float*)d_in[4];
    const float* bq    = (const float*)d_in[5];
    const float* Wk    = (const float*)d_in[6];
    const float* bk    = (const float*)d_in[7];
    const float* Wv    = (const float*)d_in[8];
    const float* bv    = (const float*)d_in[9];
    const float* rel   = (const float*)d_in[10];
    float* out = (float*)d_out;
    (void)in_sizes; (void)n_in; (void)out_size;

    const int ATTN_SMEM = SMF * (int)sizeof(float);
    cudaFuncSetAttribute(attn_kernel,
                         cudaFuncAttributeMaxDynamicSharedMemorySize, ATTN_SMEM);

    dim3 gemm_grid(Dm / 128, (Bz * Sq) / 128, 3);
    qkv_proj_kernel<<<gemm_grid, 256>>>(query, key, value, Wq, Wk, Wv, bq, bk, bv);

    dim3 attn_grid(Sq / 128, Bz * Hn);
    attn_kernel<<<attn_grid, 512, ATTN_SMEM>>>(mask, rel, out);
}